// round 1
// baseline (speedup 1.0000x reference)
#include <cuda_runtime.h>
#include <math.h>

// Problem constants
#define BB 32        // batch
#define CC 128       // FEAT_DIM
#define NPIX 4096    // H*W
#define SD 256       // SLOT_DIM
#define NS 8         // N_SLOTS
#define NH 4         // N_HEADS
#define HD 64        // HEAD_DIM
#define NJ 32        // NH*NS  (j = h*8 + s)
#define TILE_N 128

// Scratch (device globals; no allocation allowed)
__device__ float gA[BB * CC * NJ];      // per-batch folded K-projection (128x32)
__device__ float gSbias[BB * NJ];       // score bias from bk
__device__ float gM[BB * NJ * NJ * 4];  // 32*32*128 floats: M[b][j][c]
__device__ float gSsum[BB * NJ];        // sum_n attn[b][j]
__device__ float gUpd[BB * NS * SD];    // GRU output (updated slots)
__device__ float gHid[BB * NS * 2 * SD];// MLP hidden (post-ReLU)

// ---------------------------------------------------------------------------
// Kernel 1: layernorm(slots) -> q -> A = scale * Wk_head @ q^T ; also zeros M.
// One block per batch b, 256 threads.
// ---------------------------------------------------------------------------
__global__ void __launch_bounds__(256) prep_kernel(
    const float* __restrict__ slots,
    const float* __restrict__ Wq, const float* __restrict__ bq,
    const float* __restrict__ Wk, const float* __restrict__ bk,
    const float* __restrict__ g_pre, const float* __restrict__ b_pre)
{
    __shared__ float ln_s[NS][SD];
    __shared__ float q_s[NS][SD];
    int b = blockIdx.x, t = threadIdx.x;
    int w = t >> 5, lane = t & 31;

    // zero accumulators for this batch
    for (int i = t; i < NJ * CC; i += 256) gM[b * NJ * CC + i] = 0.f;
    if (t < NJ) gSsum[b * NJ + t] = 0.f;

    // LayerNorm: warp w handles slot row w
    {
        const float* row = slots + (size_t)(b * NS + w) * SD;
        float s1 = 0.f, s2 = 0.f;
        for (int k = lane; k < SD; k += 32) { float v = row[k]; s1 += v; s2 += v * v; }
        #pragma unroll
        for (int o = 16; o; o >>= 1) {
            s1 += __shfl_xor_sync(0xffffffffu, s1, o);
            s2 += __shfl_xor_sync(0xffffffffu, s2, o);
        }
        float mu = s1 * (1.f / SD);
        float var = s2 * (1.f / SD) - mu * mu;
        float rs = rsqrtf(var + 1e-5f);
        for (int k = lane; k < SD; k += 32)
            ln_s[w][k] = (row[k] - mu) * rs * g_pre[k] + b_pre[k];
    }
    __syncthreads();

    // q[s][dim] = ln[s] @ Wq + bq ; thread owns one output dim for all 8 slots
    {
        int dim = t;
        float acc[NS];
        #pragma unroll
        for (int s = 0; s < NS; s++) acc[s] = bq[dim];
        for (int k = 0; k < SD; k++) {
            float wv = Wq[k * SD + dim];
            #pragma unroll
            for (int s = 0; s < NS; s++) acc[s] += ln_s[s][k] * wv;
        }
        #pragma unroll
        for (int s = 0; s < NS; s++) q_s[s][dim] = acc[s];
    }
    __syncthreads();

    const float scale = 0.125f; // HEAD_DIM^-0.5 = 64^-0.5

    // A[c][j] = scale * sum_d Wk[c][h*64+d] * q[s][h*64+d]
    for (int idx = t; idx < CC * NJ; idx += 256) {
        int c = idx >> 5, j = idx & 31;
        int h = j >> 3, s = j & 7;
        const float* wk = Wk + c * SD + h * HD;
        const float* qq = &q_s[s][h * HD];
        float acc = 0.f;
        #pragma unroll 8
        for (int d = 0; d < HD; d++) acc += wk[d] * qq[d];
        gA[b * CC * NJ + idx] = acc * scale;
    }
    // sbias[j] = scale * sum_d bk[h*64+d] * q[s][h*64+d]
    if (t < NJ) {
        int j = t, h = j >> 3, s = j & 7;
        float acc = 0.f;
        for (int d = 0; d < HD; d++) acc += bk[h * HD + d] * q_s[s][h * HD + d];
        gSbias[b * NJ + j] = acc * scale;
    }
}

// ---------------------------------------------------------------------------
// Kernel 2 (heavy): per (b, n-tile): scores -> softmax-over-slots -> M partials
// grid (NPIX/TILE_N, B), 256 threads, ~96KB dynamic smem.
// ---------------------------------------------------------------------------
__global__ void __launch_bounds__(256) main_kernel(const float* __restrict__ features)
{
    extern __shared__ float sm[];
    float* featT = sm;                      // [C][TILE_N]
    float* A_s   = featT + CC * TILE_N;     // [C][NJ]
    float* attn  = A_s + CC * NJ;           // [NJ][TILE_N]
    float* sb    = attn + NJ * TILE_N;      // [NJ]

    int tile = blockIdx.x, b = blockIdx.y;
    int t = threadIdx.x;
    int n0 = tile * TILE_N;

    const float* fb = features + (size_t)b * CC * NPIX + n0;
    for (int idx = t; idx < CC * TILE_N; idx += 256) {
        int c = idx >> 7, nn = idx & (TILE_N - 1);
        featT[idx] = fb[c * NPIX + nn];   // gmem coalesced over nn
    }
    for (int idx = t; idx < CC * NJ; idx += 256) A_s[idx] = gA[b * CC * NJ + idx];
    if (t < NJ) sb[t] = gSbias[b * NJ + t];
    __syncthreads();

    // Phase 1: scores[n][j] = featT[:, n] . A[:, j]  (4x4 register tile)
    {
        int jg = t & 7, ng = t >> 3;
        int nb = ng * 4, jb = jg * 4;
        float acc[4][4];
        #pragma unroll
        for (int i = 0; i < 4; i++)
            #pragma unroll
            for (int u = 0; u < 4; u++) acc[i][u] = 0.f;
        #pragma unroll 4
        for (int c = 0; c < CC; c++) {
            float4 f = *(const float4*)&featT[c * TILE_N + nb];
            float4 a = *(const float4*)&A_s[c * NJ + jb];
            float fa[4] = {f.x, f.y, f.z, f.w};
            float aa[4] = {a.x, a.y, a.z, a.w};
            #pragma unroll
            for (int i = 0; i < 4; i++)
                #pragma unroll
                for (int u = 0; u < 4; u++) acc[i][u] += fa[i] * aa[u];
        }
        #pragma unroll
        for (int u = 0; u < 4; u++) {
            float bias = sb[jb + u];
            #pragma unroll
            for (int i = 0; i < 4; i++)
                attn[(jb + u) * TILE_N + nb + i] = acc[i][u] + bias;
        }
    }
    __syncthreads();

    // Phase 2: softmax over slots s (8 values) per (n, h)
    for (int task = t; task < TILE_N * NH; task += 256) {
        int n = task & (TILE_N - 1), h = task >> 7;
        float v[NS];
        float mx = -1e30f;
        #pragma unroll
        for (int s = 0; s < NS; s++) {
            v[s] = attn[(h * 8 + s) * TILE_N + n];
            mx = fmaxf(mx, v[s]);
        }
        float sum = 0.f;
        #pragma unroll
        for (int s = 0; s < NS; s++) { v[s] = __expf(v[s] - mx); sum += v[s]; }
        float inv = 1.f / sum;
        #pragma unroll
        for (int s = 0; s < NS; s++) attn[(h * 8 + s) * TILE_N + n] = v[s] * inv;
    }
    __syncthreads();

    // Phase 3: M[j][c] += sum_n attn[j][n] * featT[c][n]  (4x4 tile, n-vectorized)
    {
        int jg = t & 7, cg = t >> 3;
        int jb = jg * 4, cb = cg * 4;
        float acc[4][4];
        #pragma unroll
        for (int u = 0; u < 4; u++)
            #pragma unroll
            for (int i = 0; i < 4; i++) acc[u][i] = 0.f;
        for (int nn = 0; nn < TILE_N; nn += 4) {
            float4 av[4];
            #pragma unroll
            for (int u = 0; u < 4; u++)
                av[u] = *(const float4*)&attn[(jb + u) * TILE_N + nn];
            #pragma unroll
            for (int i = 0; i < 4; i++) {
                float4 fv = *(const float4*)&featT[(cb + i) * TILE_N + nn];
                #pragma unroll
                for (int u = 0; u < 4; u++)
                    acc[u][i] += av[u].x * fv.x + av[u].y * fv.y
                               + av[u].z * fv.z + av[u].w * fv.w;
            }
        }
        float* gm = gM + b * NJ * CC;
        #pragma unroll
        for (int u = 0; u < 4; u++)
            #pragma unroll
            for (int i = 0; i < 4; i++)
                atomicAdd(&gm[(jb + u) * CC + cb + i], acc[u][i]);
    }
    // attention row sums (for bv term)
    if (t < NJ) {
        float s = 0.f;
        #pragma unroll 4
        for (int n = 0; n < TILE_N; n++) s += attn[t * TILE_N + n];
        atomicAdd(&gSsum[b * NJ + t], s);
    }
}

// ---------------------------------------------------------------------------
// Kernel 3: agg = M @ Wv + Ssum*bv, then GRU cell -> gUpd
// grid = B*4 (b, dim-quarter), 256 threads.
// ---------------------------------------------------------------------------
__global__ void __launch_bounds__(256) gru_kernel(
    const float* __restrict__ slots,
    const float* __restrict__ Wv, const float* __restrict__ bv,
    const float* __restrict__ W_ih, const float* __restrict__ b_ih,
    const float* __restrict__ W_hh, const float* __restrict__ b_hh)
{
    __shared__ float x_s[NS][SD];
    __shared__ float h_s[NS][SD];
    int b = blockIdx.x >> 2, quarter = blockIdx.x & 3;
    int t = threadIdx.x;

    // full agg rows needed for the GRU dots (K=256), computed redundantly x4
    for (int idx = t; idx < NS * SD; idx += 256) {
        int s = idx >> 8, dim = idx & (SD - 1);
        int h = dim >> 6, j = h * 8 + s;
        float acc = gSsum[b * NJ + j] * bv[dim];
        const float* gm = gM + b * NJ * CC + j * CC;
        #pragma unroll 4
        for (int c = 0; c < CC; c++) acc += gm[c] * Wv[c * SD + dim];
        x_s[s][dim] = acc;
        h_s[s][dim] = slots[(size_t)(b * NS + s) * SD + dim];
    }
    __syncthreads();

    for (int task = t; task < NS * 64; task += 256) {
        int s = task >> 6, dloc = task & 63;
        int dim = quarter * 64 + dloc;
        float ir = b_ih[dim],      iz = b_ih[SD + dim],   in_ = b_ih[2 * SD + dim];
        float hr = b_hh[dim],      hz = b_hh[SD + dim],   hn  = b_hh[2 * SD + dim];
        const float* wr = W_ih + (size_t)dim * SD;
        const float* wz = W_ih + (size_t)(SD + dim) * SD;
        const float* wn = W_ih + (size_t)(2 * SD + dim) * SD;
        const float* vr = W_hh + (size_t)dim * SD;
        const float* vz = W_hh + (size_t)(SD + dim) * SD;
        const float* vn = W_hh + (size_t)(2 * SD + dim) * SD;
        #pragma unroll 4
        for (int k = 0; k < SD; k++) {
            float xk = x_s[s][k], hk = h_s[s][k];
            ir += xk * wr[k]; iz += xk * wz[k]; in_ += xk * wn[k];
            hr += hk * vr[k]; hz += hk * vz[k]; hn += hk * vn[k];
        }
        float r = 1.f / (1.f + expf(-(ir + hr)));
        float z = 1.f / (1.f + expf(-(iz + hz)));
        float nn = tanhf(in_ + r * hn);
        float hp = h_s[s][dim];
        gUpd[(size_t)(b * NS + s) * SD + dim] = (1.f - z) * nn + z * hp;
    }
}

// ---------------------------------------------------------------------------
// Kernel 4: hidden = relu(LN(updated) @ W1 + b1)   grid = B*4 (m-chunks)
// ---------------------------------------------------------------------------
__global__ void __launch_bounds__(256) mlp1_kernel(
    const float* __restrict__ g_post, const float* __restrict__ b_post,
    const float* __restrict__ W1, const float* __restrict__ b1)
{
    __shared__ float ln_s[NS][SD];
    int b = blockIdx.x >> 2, mc = blockIdx.x & 3;
    int t = threadIdx.x, w = t >> 5, lane = t & 31;
    {
        const float* row = gUpd + (size_t)(b * NS + w) * SD;
        float s1 = 0.f, s2 = 0.f;
        for (int k = lane; k < SD; k += 32) { float v = row[k]; s1 += v; s2 += v * v; }
        #pragma unroll
        for (int o = 16; o; o >>= 1) {
            s1 += __shfl_xor_sync(0xffffffffu, s1, o);
            s2 += __shfl_xor_sync(0xffffffffu, s2, o);
        }
        float mu = s1 * (1.f / SD);
        float var = s2 * (1.f / SD) - mu * mu;
        float rs = rsqrtf(var + 1e-5f);
        for (int k = lane; k < SD; k += 32)
            ln_s[w][k] = (row[k] - mu) * rs * g_post[k] + b_post[k];
    }
    __syncthreads();

    for (int idx = t; idx < NS * 128; idx += 256) {
        int s = idx >> 7, mloc = idx & 127;
        int m = mc * 128 + mloc;
        float acc = b1[m];
        #pragma unroll 4
        for (int k = 0; k < SD; k++) acc += ln_s[s][k] * W1[k * (2 * SD) + m];
        gHid[(size_t)(b * NS + s) * (2 * SD) + m] = fmaxf(acc, 0.f);
    }
}

// ---------------------------------------------------------------------------
// Kernel 5: out = updated + hidden @ W2 + b2   grid = B*4 (dim-chunks)
// ---------------------------------------------------------------------------
__global__ void __launch_bounds__(256) mlp2_kernel(
    const float* __restrict__ W2, const float* __restrict__ b2,
    float* __restrict__ out)
{
    __shared__ float hid_s[NS][2 * SD];
    int b = blockIdx.x >> 2, dc = blockIdx.x & 3;
    int t = threadIdx.x;
    for (int idx = t; idx < NS * 2 * SD; idx += 256)
        hid_s[idx >> 9][idx & 511] = gHid[(size_t)b * NS * 2 * SD + idx];
    __syncthreads();

    for (int task = t; task < NS * 64; task += 256) {
        int s = task >> 6, dloc = task & 63;
        int dim = dc * 64 + dloc;
        float acc = b2[dim];
        #pragma unroll 4
        for (int m = 0; m < 2 * SD; m++) acc += hid_s[s][m] * W2[m * SD + dim];
        size_t off = (size_t)(b * NS + s) * SD + dim;
        out[off] = gUpd[off] + acc;
    }
}

// ---------------------------------------------------------------------------
extern "C" void kernel_launch(void* const* d_in, const int* in_sizes, int n_in,
                              void* d_out, int out_size)
{
    const float* features = (const float*)d_in[0];
    const float* slots    = (const float*)d_in[1];
    const float* Wq   = (const float*)d_in[2];
    const float* bq   = (const float*)d_in[3];
    const float* Wk   = (const float*)d_in[4];
    const float* bk   = (const float*)d_in[5];
    const float* Wv   = (const float*)d_in[6];
    const float* bv   = (const float*)d_in[7];
    const float* W_ih = (const float*)d_in[8];
    const float* b_ih = (const float*)d_in[9];
    const float* W_hh = (const float*)d_in[10];
    const float* b_hh = (const float*)d_in[11];
    const float* g_pre  = (const float*)d_in[12];
    const float* b_pre  = (const float*)d_in[13];
    const float* g_post = (const float*)d_in[14];
    const float* b_post = (const float*)d_in[15];
    const float* W1 = (const float*)d_in[16];
    const float* b1 = (const float*)d_in[17];
    const float* W2 = (const float*)d_in[18];
    const float* b2 = (const float*)d_in[19];
    float* out = (float*)d_out;

    prep_kernel<<<BB, 256>>>(slots, Wq, bq, Wk, bk, g_pre, b_pre);

    size_t smem = (size_t)(CC * TILE_N + CC * NJ + NJ * TILE_N + NJ) * sizeof(float);
    cudaFuncSetAttribute(main_kernel, cudaFuncAttributeMaxDynamicSharedMemorySize, (int)smem);
    main_kernel<<<dim3(NPIX / TILE_N, BB), 256, smem>>>(features);

    gru_kernel<<<BB * 4, 256>>>(slots, Wv, bv, W_ih, b_ih, W_hh, b_hh);
    mlp1_kernel<<<BB * 4, 256>>>(g_post, b_post, W1, b1);
    mlp2_kernel<<<BB * 4, 256>>>(W2, b2, out);
}

// round 2
// speedup vs baseline: 2.3101x; 2.3101x over previous
#include <cuda_runtime.h>
#include <math.h>

// Problem constants
#define BB 32        // batch
#define CC 128       // FEAT_DIM
#define NPIX 4096    // H*W
#define SD 256       // SLOT_DIM
#define NS 8         // N_SLOTS
#define NH 4         // N_HEADS
#define HD 64        // HEAD_DIM
#define NJ 32        // NH*NS  (j = h*8 + s)
#define TILE_N 128
#define NROWS 256    // BB*NS flattened rows

// Scratch (device globals; no allocation allowed)
__device__ float gA[BB * CC * NJ];      // per-batch folded K-projection (128x32)
__device__ float gSbias[BB * NJ];       // score bias from bk
__device__ float gM[BB * NJ * CC];      // M[b][j][c]
__device__ float gSsum[BB * NJ];        // sum_n attn[b][j]
__device__ float gAgg[NROWS * SD];      // agg (GRU input x), [row][dim]
__device__ float gUpd[NROWS * SD];      // GRU output (updated slots)
__device__ float gLN[NROWS * SD];       // post-LN of updated
__device__ float gHid[NROWS * 2 * SD];  // MLP hidden (post-ReLU)

// ---------------------------------------------------------------------------
// Kernel 1: layernorm(slots) -> q -> A = scale * Wk_head @ q^T ; also zeros M.
// One block per batch b, 256 threads.
// ---------------------------------------------------------------------------
__global__ void __launch_bounds__(256) prep_kernel(
    const float* __restrict__ slots,
    const float* __restrict__ Wq, const float* __restrict__ bq,
    const float* __restrict__ Wk, const float* __restrict__ bk,
    const float* __restrict__ g_pre, const float* __restrict__ b_pre)
{
    __shared__ float ln_s[NS][SD];
    __shared__ float q_s[NS][SD];
    int b = blockIdx.x, t = threadIdx.x;
    int w = t >> 5, lane = t & 31;

    for (int i = t; i < NJ * CC; i += 256) gM[b * NJ * CC + i] = 0.f;
    if (t < NJ) gSsum[b * NJ + t] = 0.f;

    // LayerNorm: warp w handles slot row w
    {
        const float* row = slots + (size_t)(b * NS + w) * SD;
        float s1 = 0.f, s2 = 0.f;
        for (int k = lane; k < SD; k += 32) { float v = row[k]; s1 += v; s2 += v * v; }
        #pragma unroll
        for (int o = 16; o; o >>= 1) {
            s1 += __shfl_xor_sync(0xffffffffu, s1, o);
            s2 += __shfl_xor_sync(0xffffffffu, s2, o);
        }
        float mu = s1 * (1.f / SD);
        float var = s2 * (1.f / SD) - mu * mu;
        float rs = rsqrtf(var + 1e-5f);
        for (int k = lane; k < SD; k += 32)
            ln_s[w][k] = (row[k] - mu) * rs * g_pre[k] + b_pre[k];
    }
    __syncthreads();

    // q[s][dim] = ln[s] @ Wq + bq ; thread owns one output dim for all 8 slots
    {
        int dim = t;
        float acc[NS];
        #pragma unroll
        for (int s = 0; s < NS; s++) acc[s] = bq[dim];
        #pragma unroll 8
        for (int k = 0; k < SD; k++) {
            float wv = Wq[k * SD + dim];
            #pragma unroll
            for (int s = 0; s < NS; s++) acc[s] += ln_s[s][k] * wv;
        }
        #pragma unroll
        for (int s = 0; s < NS; s++) q_s[s][dim] = acc[s];
    }
    __syncthreads();

    const float scale = 0.125f; // HEAD_DIM^-0.5

    for (int idx = t; idx < CC * NJ; idx += 256) {
        int c = idx >> 5, j = idx & 31;
        int h = j >> 3, s = j & 7;
        const float* wk = Wk + c * SD + h * HD;
        const float* qq = &q_s[s][h * HD];
        float acc = 0.f;
        #pragma unroll 8
        for (int d = 0; d < HD; d++) acc += wk[d] * qq[d];
        gA[b * CC * NJ + idx] = acc * scale;
    }
    if (t < NJ) {
        int j = t, h = j >> 3, s = j & 7;
        float acc = 0.f;
        for (int d = 0; d < HD; d++) acc += bk[h * HD + d] * q_s[s][h * HD + d];
        gSbias[b * NJ + j] = acc * scale;
    }
}

// ---------------------------------------------------------------------------
// Kernel 2 (heavy): per (b, n-tile): scores -> softmax-over-slots -> M partials
// ---------------------------------------------------------------------------
__global__ void __launch_bounds__(256) main_kernel(const float* __restrict__ features)
{
    extern __shared__ float sm[];
    float* featT = sm;                      // [C][TILE_N]
    float* A_s   = featT + CC * TILE_N;     // [C][NJ]
    float* attn  = A_s + CC * NJ;           // [NJ][TILE_N]
    float* sb    = attn + NJ * TILE_N;      // [NJ]

    int tile = blockIdx.x, b = blockIdx.y;
    int t = threadIdx.x;
    int n0 = tile * TILE_N;

    const float* fb = features + (size_t)b * CC * NPIX + n0;
    // float4 vectorized loads (coalesced over n)
    for (int i = t; i < CC * TILE_N / 4; i += 256) {
        int c = i >> 5, n4 = i & 31;
        ((float4*)featT)[i] = ((const float4*)(fb + (size_t)c * NPIX))[n4];
    }
    for (int i = t; i < CC * NJ / 4; i += 256)
        ((float4*)A_s)[i] = ((const float4*)(gA + b * CC * NJ))[i];
    if (t < NJ) sb[t] = gSbias[b * NJ + t];
    __syncthreads();

    // Phase 1: scores[n][j] = featT[:, n] . A[:, j]  (4x4 register tile)
    {
        int jg = t & 7, ng = t >> 3;
        int nb = ng * 4, jb = jg * 4;
        float acc[4][4];
        #pragma unroll
        for (int i = 0; i < 4; i++)
            #pragma unroll
            for (int u = 0; u < 4; u++) acc[i][u] = 0.f;
        #pragma unroll 4
        for (int c = 0; c < CC; c++) {
            float4 f = *(const float4*)&featT[c * TILE_N + nb];
            float4 a = *(const float4*)&A_s[c * NJ + jb];
            float fa[4] = {f.x, f.y, f.z, f.w};
            float aa[4] = {a.x, a.y, a.z, a.w};
            #pragma unroll
            for (int i = 0; i < 4; i++)
                #pragma unroll
                for (int u = 0; u < 4; u++) acc[i][u] += fa[i] * aa[u];
        }
        #pragma unroll
        for (int u = 0; u < 4; u++) {
            float bias = sb[jb + u];
            #pragma unroll
            for (int i = 0; i < 4; i++)
                attn[(jb + u) * TILE_N + nb + i] = acc[i][u] + bias;
        }
    }
    __syncthreads();

    // Phase 2: softmax over slots s (8 values) per (n, h)
    for (int task = t; task < TILE_N * NH; task += 256) {
        int n = task & (TILE_N - 1), h = task >> 7;
        float v[NS];
        float mx = -1e30f;
        #pragma unroll
        for (int s = 0; s < NS; s++) {
            v[s] = attn[(h * 8 + s) * TILE_N + n];
            mx = fmaxf(mx, v[s]);
        }
        float sum = 0.f;
        #pragma unroll
        for (int s = 0; s < NS; s++) { v[s] = __expf(v[s] - mx); sum += v[s]; }
        float inv = 1.f / sum;
        #pragma unroll
        for (int s = 0; s < NS; s++) attn[(h * 8 + s) * TILE_N + n] = v[s] * inv;
    }
    __syncthreads();

    // Phase 3: M[j][c] += sum_n attn[j][n] * featT[c][n]
    {
        int jg = t & 7, cg = t >> 3;
        int jb = jg * 4, cb = cg * 4;
        float acc[4][4];
        #pragma unroll
        for (int u = 0; u < 4; u++)
            #pragma unroll
            for (int i = 0; i < 4; i++) acc[u][i] = 0.f;
        for (int nn = 0; nn < TILE_N; nn += 4) {
            float4 av[4];
            #pragma unroll
            for (int u = 0; u < 4; u++)
                av[u] = *(const float4*)&attn[(jb + u) * TILE_N + nn];
            #pragma unroll
            for (int i = 0; i < 4; i++) {
                float4 fv = *(const float4*)&featT[(cb + i) * TILE_N + nn];
                #pragma unroll
                for (int u = 0; u < 4; u++)
                    acc[u][i] += av[u].x * fv.x + av[u].y * fv.y
                               + av[u].z * fv.z + av[u].w * fv.w;
            }
        }
        float* gm = gM + b * NJ * CC;
        #pragma unroll
        for (int u = 0; u < 4; u++)
            #pragma unroll
            for (int i = 0; i < 4; i++)
                atomicAdd(&gm[(jb + u) * CC + cb + i], acc[u][i]);
    }
    if (t < NJ) {
        float s = 0.f;
        #pragma unroll 4
        for (int n = 0; n < TILE_N; n++) s += attn[t * TILE_N + n];
        atomicAdd(&gSsum[b * NJ + t], s);
    }
}

// ---------------------------------------------------------------------------
// Kernel 3: agg[row][dim] = M[b][j] @ Wv[:,dim] + Ssum*bv. Block per (b, head).
// ---------------------------------------------------------------------------
__global__ void __launch_bounds__(256) agg_kernel(
    const float* __restrict__ Wv, const float* __restrict__ bv)
{
    __shared__ float Ms[NS][CC];     // 4 KB
    __shared__ float Wvs[CC][HD];    // 32 KB
    int b = blockIdx.x >> 2, h = blockIdx.x & 3;
    int t = threadIdx.x;

    // load M rows for this (b, h): j = h*8+s
    {
        int s = t >> 5, c4 = t & 31;
        ((float4*)&Ms[s][0])[c4] =
            ((const float4*)(gM + (size_t)b * NJ * CC + (h * 8 + s) * CC))[c4];
    }
    // load Wv column block [128][64] at col offset h*64
    #pragma unroll
    for (int j = 0; j < 8; j++) {
        int i = t + j * 256;
        int c = i >> 4, d4 = i & 15;
        ((float4*)&Wvs[c][0])[d4] =
            ((const float4*)(Wv + (size_t)c * SD + h * HD))[d4];
    }
    __syncthreads();

    #pragma unroll
    for (int rep = 0; rep < 2; rep++) {
        int o = t + rep * 256;
        int s = o >> 6, d = o & 63;
        int j = h * 8 + s;
        float acc = gSsum[b * NJ + j] * bv[h * HD + d];
        #pragma unroll 8
        for (int c = 0; c < CC; c++) acc += Ms[s][c] * Wvs[c][d];
        gAgg[(size_t)(b * NS + s) * SD + h * HD + d] = acc;
    }
}

// ---------------------------------------------------------------------------
// Kernel 4: GRU as tiled GEMM. Grid (8 m-tiles, 8 dim-tiles); tile 32x32x3gates.
// K=256 vs gAgg/W_ih, then K=256 vs slots/W_hh. KT=32 smem slabs.
// ---------------------------------------------------------------------------
#define KT 32
__global__ void __launch_bounds__(256) gru_kernel(
    const float* __restrict__ slots,
    const float* __restrict__ W_ih, const float* __restrict__ b_ih,
    const float* __restrict__ W_hh, const float* __restrict__ b_hh)
{
    __shared__ float As[32][KT + 1];        // [m][k]
    __shared__ float Bs[3][32][KT + 1];     // [gate][d][k]
    int m0 = blockIdx.x * 32, dim0 = blockIdx.y * 32;
    int t = threadIdx.x;
    int di = t & 15, mi = t >> 4;           // thread tile: 2m x 2d x gates

    float acc_r[2][2] = {{0,0},{0,0}}, acc_z[2][2] = {{0,0},{0,0}};
    float acc_in[2][2] = {{0,0},{0,0}}, acc_hn[2][2] = {{0,0},{0,0}};

    int lm = t >> 3, lk = t & 7;            // loader mapping (row, k-chunk)

    #pragma unroll
    for (int phase = 0; phase < 2; phase++) {
        const float* Ag = phase ? slots : gAgg;      // [256][256]
        const float* Wg = phase ? W_hh : W_ih;       // [768][256]
        for (int k0 = 0; k0 < SD; k0 += KT) {
            // stage A slab: rows m0..m0+31, k0..k0+31
            {
                float4 v = *(const float4*)(Ag + (size_t)(m0 + lm) * SD + k0 + lk * 4);
                As[lm][lk * 4 + 0] = v.x; As[lm][lk * 4 + 1] = v.y;
                As[lm][lk * 4 + 2] = v.z; As[lm][lk * 4 + 3] = v.w;
            }
            // stage B slabs: 3 gates x 32 dims x 32 k
            #pragma unroll
            for (int g = 0; g < 3; g++) {
                float4 v = *(const float4*)(Wg + (size_t)(g * SD + dim0 + lm) * SD + k0 + lk * 4);
                Bs[g][lm][lk * 4 + 0] = v.x; Bs[g][lm][lk * 4 + 1] = v.y;
                Bs[g][lm][lk * 4 + 2] = v.z; Bs[g][lm][lk * 4 + 3] = v.w;
            }
            __syncthreads();
            #pragma unroll 8
            for (int k = 0; k < KT; k++) {
                float a0 = As[mi * 2 + 0][k], a1 = As[mi * 2 + 1][k];
                float br0 = Bs[0][di * 2 + 0][k], br1 = Bs[0][di * 2 + 1][k];
                float bz0 = Bs[1][di * 2 + 0][k], bz1 = Bs[1][di * 2 + 1][k];
                float bn0 = Bs[2][di * 2 + 0][k], bn1 = Bs[2][di * 2 + 1][k];
                acc_r[0][0] += a0 * br0; acc_r[0][1] += a0 * br1;
                acc_r[1][0] += a1 * br0; acc_r[1][1] += a1 * br1;
                acc_z[0][0] += a0 * bz0; acc_z[0][1] += a0 * bz1;
                acc_z[1][0] += a1 * bz0; acc_z[1][1] += a1 * bz1;
                if (phase == 0) {
                    acc_in[0][0] += a0 * bn0; acc_in[0][1] += a0 * bn1;
                    acc_in[1][0] += a1 * bn0; acc_in[1][1] += a1 * bn1;
                } else {
                    acc_hn[0][0] += a0 * bn0; acc_hn[0][1] += a0 * bn1;
                    acc_hn[1][0] += a1 * bn0; acc_hn[1][1] += a1 * bn1;
                }
            }
            __syncthreads();
        }
    }

    // epilogue
    #pragma unroll
    for (int ii = 0; ii < 2; ii++) {
        int m = m0 + mi * 2 + ii;
        #pragma unroll
        for (int jj = 0; jj < 2; jj++) {
            int d = dim0 + di * 2 + jj;
            float r = 1.f / (1.f + expf(-(acc_r[ii][jj] + b_ih[d] + b_hh[d])));
            float z = 1.f / (1.f + expf(-(acc_z[ii][jj] + b_ih[SD + d] + b_hh[SD + d])));
            float nn = tanhf(acc_in[ii][jj] + b_ih[2 * SD + d]
                             + r * (acc_hn[ii][jj] + b_hh[2 * SD + d]));
            float hp = slots[(size_t)m * SD + d];
            gUpd[(size_t)m * SD + d] = (1.f - z) * nn + z * hp;
        }
    }
}

// ---------------------------------------------------------------------------
// Kernel 5: LN(gUpd) -> gLN. 32 blocks x 8 warps (1 row per warp).
// ---------------------------------------------------------------------------
__global__ void __launch_bounds__(256) ln_kernel(
    const float* __restrict__ g_post, const float* __restrict__ b_post)
{
    int row = blockIdx.x * 8 + (threadIdx.x >> 5);
    int lane = threadIdx.x & 31;
    const float* src = gUpd + (size_t)row * SD;
    float s1 = 0.f, s2 = 0.f;
    for (int k = lane; k < SD; k += 32) { float v = src[k]; s1 += v; s2 += v * v; }
    #pragma unroll
    for (int o = 16; o; o >>= 1) {
        s1 += __shfl_xor_sync(0xffffffffu, s1, o);
        s2 += __shfl_xor_sync(0xffffffffu, s2, o);
    }
    float mu = s1 * (1.f / SD);
    float var = s2 * (1.f / SD) - mu * mu;
    float rs = rsqrtf(var + 1e-5f);
    float* dst = gLN + (size_t)row * SD;
    for (int k = lane; k < SD; k += 32)
        dst[k] = (src[k] - mu) * rs * g_post[k] + b_post[k];
}

// ---------------------------------------------------------------------------
// Kernel 6: gHid = relu(gLN @ W1 + b1). NN GEMM 256x512, K=256.
// Grid (8 m, 8 n64). Tile 32x64, thread 2m x 4n.
// ---------------------------------------------------------------------------
__global__ void __launch_bounds__(256) mlp1_kernel(
    const float* __restrict__ W1, const float* __restrict__ b1)
{
    __shared__ float As[32][KT + 1];     // [m][k]
    __shared__ float Bs[KT][68];         // [k][n], padded to 68 (16B aligned rows)
    int m0 = blockIdx.x * 32, n0 = blockIdx.y * 64;
    int t = threadIdx.x;
    int ni = t & 15, mi = t >> 4;
    float acc[2][4] = {{0,0,0,0},{0,0,0,0}};
    int lm = t >> 3, lk = t & 7;

    for (int k0 = 0; k0 < SD; k0 += KT) {
        {
            float4 v = *(const float4*)(gLN + (size_t)(m0 + lm) * SD + k0 + lk * 4);
            As[lm][lk * 4 + 0] = v.x; As[lm][lk * 4 + 1] = v.y;
            As[lm][lk * 4 + 2] = v.z; As[lm][lk * 4 + 3] = v.w;
        }
        #pragma unroll
        for (int rep = 0; rep < 2; rep++) {
            int i = t + rep * 256;
            int k = i >> 4, nc = i & 15;
            float4 v = *(const float4*)(W1 + (size_t)(k0 + k) * (2 * SD) + n0 + nc * 4);
            *(float4*)&Bs[k][nc * 4] = v;
        }
        __syncthreads();
        #pragma unroll 8
        for (int k = 0; k < KT; k++) {
            float a0 = As[mi * 2 + 0][k], a1 = As[mi * 2 + 1][k];
            float4 bv4 = *(const float4*)&Bs[k][ni * 4];
            acc[0][0] += a0 * bv4.x; acc[0][1] += a0 * bv4.y;
            acc[0][2] += a0 * bv4.z; acc[0][3] += a0 * bv4.w;
            acc[1][0] += a1 * bv4.x; acc[1][1] += a1 * bv4.y;
            acc[1][2] += a1 * bv4.z; acc[1][3] += a1 * bv4.w;
        }
        __syncthreads();
    }
    #pragma unroll
    for (int ii = 0; ii < 2; ii++) {
        int m = m0 + mi * 2 + ii;
        #pragma unroll
        for (int u = 0; u < 4; u++) {
            int n = n0 + ni * 4 + u;
            gHid[(size_t)m * (2 * SD) + n] = fmaxf(acc[ii][u] + b1[n], 0.f);
        }
    }
}

// ---------------------------------------------------------------------------
// Kernel 7: out = gUpd + gHid @ W2 + b2. NN GEMM 256x256, K=512.
// Grid (8 m, 4 n64). Tile 32x64, thread 2m x 4n.
// ---------------------------------------------------------------------------
__global__ void __launch_bounds__(256) mlp2_kernel(
    const float* __restrict__ W2, const float* __restrict__ b2,
    float* __restrict__ out)
{
    __shared__ float As[32][KT + 1];
    __shared__ float Bs[KT][68];
    int m0 = blockIdx.x * 32, n0 = blockIdx.y * 64;
    int t = threadIdx.x;
    int ni = t & 15, mi = t >> 4;
    float acc[2][4] = {{0,0,0,0},{0,0,0,0}};
    int lm = t >> 3, lk = t & 7;

    for (int k0 = 0; k0 < 2 * SD; k0 += KT) {
        {
            float4 v = *(const float4*)(gHid + (size_t)(m0 + lm) * (2 * SD) + k0 + lk * 4);
            As[lm][lk * 4 + 0] = v.x; As[lm][lk * 4 + 1] = v.y;
            As[lm][lk * 4 + 2] = v.z; As[lm][lk * 4 + 3] = v.w;
        }
        #pragma unroll
        for (int rep = 0; rep < 2; rep++) {
            int i = t + rep * 256;
            int k = i >> 4, nc = i & 15;
            float4 v = *(const float4*)(W2 + (size_t)(k0 + k) * SD + n0 + nc * 4);
            *(float4*)&Bs[k][nc * 4] = v;
        }
        __syncthreads();
        #pragma unroll 8
        for (int k = 0; k < KT; k++) {
            float a0 = As[mi * 2 + 0][k], a1 = As[mi * 2 + 1][k];
            float4 bv4 = *(const float4*)&Bs[k][ni * 4];
            acc[0][0] += a0 * bv4.x; acc[0][1] += a0 * bv4.y;
            acc[0][2] += a0 * bv4.z; acc[0][3] += a0 * bv4.w;
            acc[1][0] += a1 * bv4.x; acc[1][1] += a1 * bv4.y;
            acc[1][2] += a1 * bv4.z; acc[1][3] += a1 * bv4.w;
        }
        __syncthreads();
    }
    #pragma unroll
    for (int ii = 0; ii < 2; ii++) {
        int m = m0 + mi * 2 + ii;
        #pragma unroll
        for (int u = 0; u < 4; u++) {
            int n = n0 + ni * 4 + u;
            out[(size_t)m * SD + n] = gUpd[(size_t)m * SD + n] + acc[ii][u] + b2[n];
        }
    }
}

// ---------------------------------------------------------------------------
extern "C" void kernel_launch(void* const* d_in, const int* in_sizes, int n_in,
                              void* d_out, int out_size)
{
    const float* features = (const float*)d_in[0];
    const float* slots    = (const float*)d_in[1];
    const float* Wq   = (const float*)d_in[2];
    const float* bq   = (const float*)d_in[3];
    const float* Wk   = (const float*)d_in[4];
    const float* bk   = (const float*)d_in[5];
    const float* Wv   = (const float*)d_in[6];
    const float* bv   = (const float*)d_in[7];
    const float* W_ih = (const float*)d_in[8];
    const float* b_ih = (const float*)d_in[9];
    const float* W_hh = (const float*)d_in[10];
    const float* b_hh = (const float*)d_in[11];
    const float* g_pre  = (const float*)d_in[12];
    const float* b_pre  = (const float*)d_in[13];
    const float* g_post = (const float*)d_in[14];
    const float* b_post = (const float*)d_in[15];
    const float* W1 = (const float*)d_in[16];
    const float* b1 = (const float*)d_in[17];
    const float* W2 = (const float*)d_in[18];
    const float* b2 = (const float*)d_in[19];
    float* out = (float*)d_out;

    prep_kernel<<<BB, 256>>>(slots, Wq, bq, Wk, bk, g_pre, b_pre);

    size_t smem = (size_t)(CC * TILE_N + CC * NJ + NJ * TILE_N + NJ) * sizeof(float);
    cudaFuncSetAttribute(main_kernel, cudaFuncAttributeMaxDynamicSharedMemorySize, (int)smem);
    main_kernel<<<dim3(NPIX / TILE_N, BB), 256, smem>>>(features);

    agg_kernel<<<BB * NH, 256>>>(Wv, bv);
    gru_kernel<<<dim3(NROWS / 32, SD / 32), 256>>>(slots, W_ih, b_ih, W_hh, b_hh);
    ln_kernel<<<NROWS / 8, 256>>>(g_post, b_post);
    mlp1_kernel<<<dim3(NROWS / 32, (2 * SD) / 64), 256>>>(W1, b1);
    mlp2_kernel<<<dim3(NROWS / 32, SD / 64), 256>>>(W2, b2, out);
}

// round 3
// speedup vs baseline: 4.5029x; 1.9492x over previous
#include <cuda_runtime.h>
#include <math.h>

// Problem constants
#define BB 32        // batch
#define CC 128       // FEAT_DIM
#define NPIX 4096    // H*W
#define SD 256       // SLOT_DIM
#define NS 8         // N_SLOTS
#define NH 4         // N_HEADS
#define HD 64        // HEAD_DIM
#define NJ 32        // NH*NS  (j = h*8 + s)
#define TILE_N 128
#define NROWS 256    // BB*NS flattened rows
#define FST 132      // featT smem row stride (padded)
#define AST 132      // attn smem row stride (padded)
#define KT 32
#define RS (NROWS * SD)

// Scratch (device globals; no allocation allowed)
__device__ float gA[BB * CC * NJ];      // per-batch folded K-projection (128x32)
__device__ float gSbias[BB * NJ];       // score bias from bk
__device__ float gM[BB * NJ * CC];      // M[b][j][c]
__device__ float gSsum[BB * NJ];        // sum_n attn[b][j]
__device__ float gAgg[RS];              // agg (GRU input x), [row][dim]
__device__ float gUpd[RS];              // GRU output (updated slots)
__device__ float gLN[RS];               // post-LN of updated
__device__ float gHid[NROWS * 2 * SD];  // MLP hidden (post-ReLU)
__device__ float gPart[6 * RS];         // GRU gate partials: [phase*3+gate][m][d]

// ---------------------------------------------------------------------------
// Kernel 1: LN(slots) -> q(half) -> A fold for a head-pair. grid = BB*2.
// ---------------------------------------------------------------------------
__global__ void __launch_bounds__(256) prep_kernel(
    const float* __restrict__ slots,
    const float* __restrict__ Wq, const float* __restrict__ bq,
    const float* __restrict__ Wk, const float* __restrict__ bk,
    const float* __restrict__ g_pre, const float* __restrict__ b_pre)
{
    __shared__ float ln_s[NS][SD];
    __shared__ float qp[NS][128];
    __shared__ float q_s[NS][128];
    int b = blockIdx.x >> 1, hp = blockIdx.x & 1;   // heads 2hp, 2hp+1
    int t = threadIdx.x;
    int w = t >> 5, lane = t & 31;

    // zero the 16 M rows + Ssum slots this block owns
    for (int i = t; i < 16 * CC; i += 256)
        gM[b * NJ * CC + hp * 16 * CC + i] = 0.f;
    if (t < 16) gSsum[b * NJ + hp * 16 + t] = 0.f;

    // LayerNorm: warp w handles slot row w (full SD)
    {
        const float* row = slots + (size_t)(b * NS + w) * SD;
        float s1 = 0.f, s2 = 0.f;
        for (int k = lane; k < SD; k += 32) { float v = row[k]; s1 += v; s2 += v * v; }
        #pragma unroll
        for (int o = 16; o; o >>= 1) {
            s1 += __shfl_xor_sync(0xffffffffu, s1, o);
            s2 += __shfl_xor_sync(0xffffffffu, s2, o);
        }
        float mu = s1 * (1.f / SD);
        float var = s2 * (1.f / SD) - mu * mu;
        float rs = rsqrtf(var + 1e-5f);
        for (int k = lane; k < SD; k += 32)
            ln_s[w][k] = (row[k] - mu) * rs * g_pre[k] + b_pre[k];
    }
    __syncthreads();

    // q for dims [hp*128, hp*128+128): K-split 2
    {
        int dimL = t & 127, ks = t >> 7;
        int dim = hp * 128 + dimL;
        float acc[NS];
        #pragma unroll
        for (int s = 0; s < NS; s++) acc[s] = 0.f;
        int kb = ks * 128;
        #pragma unroll 8
        for (int k = kb; k < kb + 128; k++) {
            float wv = Wq[k * SD + dim];
            #pragma unroll
            for (int s = 0; s < NS; s++) acc[s] += ln_s[s][k] * wv;
        }
        if (ks == 1) {
            #pragma unroll
            for (int s = 0; s < NS; s++) qp[s][dimL] = acc[s];
        }
        __syncthreads();
        if (ks == 0) {
            float bqv = bq[dim];
            #pragma unroll
            for (int s = 0; s < NS; s++) q_s[s][dimL] = acc[s] + qp[s][dimL] + bqv;
        }
    }
    __syncthreads();

    const float scale = 0.125f;

    // A[c][j] for the 16 j of this head-pair
    for (int idx = t; idx < CC * 16; idx += 256) {
        int c = idx >> 4, jl = idx & 15;
        int hl = jl >> 3, s = jl & 7;
        const float* wk = Wk + (size_t)c * SD + (2 * hp + hl) * HD;
        const float* qq = &q_s[s][hl * HD];
        float acc = 0.f;
        #pragma unroll 8
        for (int d = 0; d < HD; d++) acc += wk[d] * qq[d];
        gA[b * CC * NJ + c * NJ + hp * 16 + jl] = acc * scale;
    }
    if (t < 16) {
        int jl = t, hl = jl >> 3, s = jl & 7;
        float acc = 0.f;
        for (int d = 0; d < HD; d++)
            acc += bk[(2 * hp + hl) * HD + d] * q_s[s][hl * HD + d];
        gSbias[b * NJ + hp * 16 + jl] = acc * scale;
    }
}

// ---------------------------------------------------------------------------
// Kernel 2 (heavy): scores + fused softmax + M partials. grid (32, 32).
// ---------------------------------------------------------------------------
__global__ void __launch_bounds__(256) main_kernel(const float* __restrict__ features)
{
    extern __shared__ float sm[];
    float* featT = sm;                     // [CC][FST]
    float* A_s   = featT + CC * FST;       // [CC][NJ]
    float* attn  = A_s + CC * NJ;          // [NJ][AST]

    int tile = blockIdx.x, b = blockIdx.y;
    int t = threadIdx.x;
    int n0 = tile * TILE_N;

    const float* fb = features + (size_t)b * CC * NPIX + n0;
    for (int i = t; i < CC * TILE_N / 4; i += 256) {
        int c = i >> 5, n4 = i & 31;
        ((float4*)(featT + c * FST))[n4] = ((const float4*)(fb + (size_t)c * NPIX))[n4];
    }
    for (int i = t; i < CC * NJ / 4; i += 256)
        ((float4*)A_s)[i] = ((const float4*)(gA + b * CC * NJ))[i];
    __syncthreads();

    // Phase 1: scores + bias + fused softmax (pair t^1 holds the other 4 slots)
    {
        int jg = t & 7, ng = t >> 3;
        int nb = ng * 4, jb = jg * 4;
        float sbv[4];
        #pragma unroll
        for (int u = 0; u < 4; u++) sbv[u] = gSbias[b * NJ + jb + u];

        float acc[4][4];
        #pragma unroll
        for (int i = 0; i < 4; i++)
            #pragma unroll
            for (int u = 0; u < 4; u++) acc[i][u] = 0.f;
        #pragma unroll 4
        for (int c = 0; c < CC; c++) {
            float4 f = *(const float4*)&featT[c * FST + nb];
            float4 a = *(const float4*)&A_s[c * NJ + jb];
            float fa[4] = {f.x, f.y, f.z, f.w};
            float aa[4] = {a.x, a.y, a.z, a.w};
            #pragma unroll
            for (int i = 0; i < 4; i++)
                #pragma unroll
                for (int u = 0; u < 4; u++) acc[i][u] += fa[i] * aa[u];
        }
        #pragma unroll
        for (int i = 0; i < 4; i++)
            #pragma unroll
            for (int u = 0; u < 4; u++) acc[i][u] += sbv[u];

        // softmax over 8 slots of a head: this thread's 4 + partner's 4
        #pragma unroll
        for (int i = 0; i < 4; i++) {
            float m = fmaxf(fmaxf(acc[i][0], acc[i][1]), fmaxf(acc[i][2], acc[i][3]));
            m = fmaxf(m, __shfl_xor_sync(0xffffffffu, m, 1));
            float s = 0.f;
            #pragma unroll
            for (int u = 0; u < 4; u++) { acc[i][u] = __expf(acc[i][u] - m); s += acc[i][u]; }
            s += __shfl_xor_sync(0xffffffffu, s, 1);
            float inv = 1.f / s;
            #pragma unroll
            for (int u = 0; u < 4; u++) acc[i][u] *= inv;
        }

        // write attn (padded rows -> conflict-free float4 STS)
        #pragma unroll
        for (int u = 0; u < 4; u++) {
            float4 v = make_float4(acc[0][u], acc[1][u], acc[2][u], acc[3][u]);
            *(float4*)&attn[(jb + u) * AST + nb] = v;
        }

        // Ssum: reduce over ng groups within warp, then coalesced global REDG
        float p[4];
        #pragma unroll
        for (int u = 0; u < 4; u++)
            p[u] = acc[0][u] + acc[1][u] + acc[2][u] + acc[3][u];
        #pragma unroll
        for (int u = 0; u < 4; u++) {
            p[u] += __shfl_xor_sync(0xffffffffu, p[u], 8);
            p[u] += __shfl_xor_sync(0xffffffffu, p[u], 16);
        }
        if ((t & 31) < 8) {
            #pragma unroll
            for (int u = 0; u < 4; u++) atomicAdd(&gSsum[b * NJ + jb + u], p[u]);
        }
    }
    __syncthreads();

    // Phase 3: warp owns 4 j rows, lane owns c = {lane, lane+32, lane+64, lane+96}
    {
        int jb = (t >> 5) * 4, cg = t & 31;
        float acc[4][4];   // [u][r]
        #pragma unroll
        for (int u = 0; u < 4; u++)
            #pragma unroll
            for (int r = 0; r < 4; r++) acc[u][r] = 0.f;
        for (int nn = 0; nn < TILE_N; nn += 4) {
            float4 av[4];
            #pragma unroll
            for (int u = 0; u < 4; u++)
                av[u] = *(const float4*)&attn[(jb + u) * AST + nn];   // broadcast
            #pragma unroll
            for (int r = 0; r < 4; r++) {
                float4 fv = *(const float4*)&featT[(cg + 32 * r) * FST + nn];
                #pragma unroll
                for (int u = 0; u < 4; u++)
                    acc[u][r] += av[u].x * fv.x + av[u].y * fv.y
                               + av[u].z * fv.z + av[u].w * fv.w;
            }
        }
        float* gm = gM + b * NJ * CC;
        #pragma unroll
        for (int u = 0; u < 4; u++)
            #pragma unroll
            for (int r = 0; r < 4; r++)
                atomicAdd(&gm[(jb + u) * CC + cg + 32 * r], acc[u][r]);  // coalesced
    }
}

// ---------------------------------------------------------------------------
// Kernel 3: agg[row][dim] = M[b][j] @ Wv[:,dim] + Ssum*bv. Block per (b, head).
// ---------------------------------------------------------------------------
__global__ void __launch_bounds__(256) agg_kernel(
    const float* __restrict__ Wv, const float* __restrict__ bv)
{
    __shared__ float Ms[NS][CC];
    __shared__ float Wvs[CC][HD];
    int b = blockIdx.x >> 2, h = blockIdx.x & 3;
    int t = threadIdx.x;
    {
        int s = t >> 5, c4 = t & 31;
        ((float4*)&Ms[s][0])[c4] =
            ((const float4*)(gM + (size_t)b * NJ * CC + (h * 8 + s) * CC))[c4];
    }
    #pragma unroll
    for (int j = 0; j < 8; j++) {
        int i = t + j * 256;
        int c = i >> 4, d4 = i & 15;
        ((float4*)&Wvs[c][0])[d4] =
            ((const float4*)(Wv + (size_t)c * SD + h * HD))[d4];
    }
    __syncthreads();
    #pragma unroll
    for (int rep = 0; rep < 2; rep++) {
        int o = t + rep * 256;
        int s = o >> 6, d = o & 63;
        int j = h * 8 + s;
        float acc = gSsum[b * NJ + j] * bv[h * HD + d];
        #pragma unroll 8
        for (int c = 0; c < CC; c++) acc += Ms[s][c] * Wvs[c][d];
        gAgg[(size_t)(b * NS + s) * SD + h * HD + d] = acc;
    }
}

// ---------------------------------------------------------------------------
// Kernel 4: GRU gate GEMM, phase-split. grid (8, 8, 2) = 128 blocks.
// ---------------------------------------------------------------------------
__global__ void __launch_bounds__(256) gru_gemm_kernel(
    const float* __restrict__ slots,
    const float* __restrict__ W_ih, const float* __restrict__ W_hh)
{
    __shared__ float As[32][KT + 1];
    __shared__ float Bs[3][32][KT + 1];
    int m0 = blockIdx.x * 32, dim0 = blockIdx.y * 32;
    int phase = blockIdx.z;
    int t = threadIdx.x;
    int di = t & 15, mi = t >> 4;

    float acc_r[2][2] = {{0,0},{0,0}}, acc_z[2][2] = {{0,0},{0,0}};
    float acc_n[2][2] = {{0,0},{0,0}};

    int lm = t >> 3, lk = t & 7;
    const float* Ag = phase ? slots : gAgg;
    const float* Wg = phase ? W_hh : W_ih;

    for (int k0 = 0; k0 < SD; k0 += KT) {
        {
            float4 v = *(const float4*)(Ag + (size_t)(m0 + lm) * SD + k0 + lk * 4);
            As[lm][lk * 4 + 0] = v.x; As[lm][lk * 4 + 1] = v.y;
            As[lm][lk * 4 + 2] = v.z; As[lm][lk * 4 + 3] = v.w;
        }
        #pragma unroll
        for (int g = 0; g < 3; g++) {
            float4 v = *(const float4*)(Wg + (size_t)(g * SD + dim0 + lm) * SD + k0 + lk * 4);
            Bs[g][lm][lk * 4 + 0] = v.x; Bs[g][lm][lk * 4 + 1] = v.y;
            Bs[g][lm][lk * 4 + 2] = v.z; Bs[g][lm][lk * 4 + 3] = v.w;
        }
        __syncthreads();
        #pragma unroll 8
        for (int k = 0; k < KT; k++) {
            float a0 = As[mi * 2 + 0][k], a1 = As[mi * 2 + 1][k];
            float br0 = Bs[0][di * 2 + 0][k], br1 = Bs[0][di * 2 + 1][k];
            float bz0 = Bs[1][di * 2 + 0][k], bz1 = Bs[1][di * 2 + 1][k];
            float bn0 = Bs[2][di * 2 + 0][k], bn1 = Bs[2][di * 2 + 1][k];
            acc_r[0][0] += a0 * br0; acc_r[0][1] += a0 * br1;
            acc_r[1][0] += a1 * br0; acc_r[1][1] += a1 * br1;
            acc_z[0][0] += a0 * bz0; acc_z[0][1] += a0 * bz1;
            acc_z[1][0] += a1 * bz0; acc_z[1][1] += a1 * bz1;
            acc_n[0][0] += a0 * bn0; acc_n[0][1] += a0 * bn1;
            acc_n[1][0] += a1 * bn0; acc_n[1][1] += a1 * bn1;
        }
        __syncthreads();
    }

    float* base = gPart + (size_t)(phase * 3) * RS;
    #pragma unroll
    for (int ii = 0; ii < 2; ii++) {
        int m = m0 + mi * 2 + ii;
        #pragma unroll
        for (int jj = 0; jj < 2; jj++) {
            int d = dim0 + di * 2 + jj;
            base[0 * RS + (size_t)m * SD + d] = acc_r[ii][jj];
            base[1 * RS + (size_t)m * SD + d] = acc_z[ii][jj];
            base[2 * RS + (size_t)m * SD + d] = acc_n[ii][jj];
        }
    }
}

// ---------------------------------------------------------------------------
// Kernel 5: GRU finalize + post-LN (fused). grid = 32, warp per row.
// ---------------------------------------------------------------------------
__global__ void __launch_bounds__(256) gru_fin_kernel(
    const float* __restrict__ slots,
    const float* __restrict__ b_ih, const float* __restrict__ b_hh,
    const float* __restrict__ g_post, const float* __restrict__ b_post)
{
    int row = blockIdx.x * 8 + (threadIdx.x >> 5);
    int lane = threadIdx.x & 31;
    float vals[8];
    float s1 = 0.f, s2 = 0.f;
    size_t ro = (size_t)row * SD;
    #pragma unroll
    for (int r8 = 0; r8 < 8; r8++) {
        int d = r8 * 32 + lane;
        float ir = gPart[0 * RS + ro + d] + b_ih[d];
        float iz = gPart[1 * RS + ro + d] + b_ih[SD + d];
        float in_ = gPart[2 * RS + ro + d] + b_ih[2 * SD + d];
        float hr = gPart[3 * RS + ro + d] + b_hh[d];
        float hz = gPart[4 * RS + ro + d] + b_hh[SD + d];
        float hn = gPart[5 * RS + ro + d] + b_hh[2 * SD + d];
        float r = 1.f / (1.f + expf(-(ir + hr)));
        float z = 1.f / (1.f + expf(-(iz + hz)));
        float nn = tanhf(in_ + r * hn);
        float hp = slots[ro + d];
        float v = (1.f - z) * nn + z * hp;
        gUpd[ro + d] = v;
        vals[r8] = v;
        s1 += v; s2 += v * v;
    }
    #pragma unroll
    for (int o = 16; o; o >>= 1) {
        s1 += __shfl_xor_sync(0xffffffffu, s1, o);
        s2 += __shfl_xor_sync(0xffffffffu, s2, o);
    }
    float mu = s1 * (1.f / SD);
    float var = s2 * (1.f / SD) - mu * mu;
    float rs = rsqrtf(var + 1e-5f);
    #pragma unroll
    for (int r8 = 0; r8 < 8; r8++) {
        int d = r8 * 32 + lane;
        gLN[ro + d] = (vals[r8] - mu) * rs * g_post[d] + b_post[d];
    }
}

// ---------------------------------------------------------------------------
// Kernel 6: gHid = relu(gLN @ W1 + b1). Grid (8, 8), tile 32x64.
// ---------------------------------------------------------------------------
__global__ void __launch_bounds__(256) mlp1_kernel(
    const float* __restrict__ W1, const float* __restrict__ b1)
{
    __shared__ float As[32][KT + 1];
    __shared__ float Bs[KT][68];
    int m0 = blockIdx.x * 32, n0 = blockIdx.y * 64;
    int t = threadIdx.x;
    int ni = t & 15, mi = t >> 4;
    float acc[2][4] = {{0,0,0,0},{0,0,0,0}};
    int lm = t >> 3, lk = t & 7;

    for (int k0 = 0; k0 < SD; k0 += KT) {
        {
            float4 v = *(const float4*)(gLN + (size_t)(m0 + lm) * SD + k0 + lk * 4);
            As[lm][lk * 4 + 0] = v.x; As[lm][lk * 4 + 1] = v.y;
            As[lm][lk * 4 + 2] = v.z; As[lm][lk * 4 + 3] = v.w;
        }
        #pragma unroll
        for (int rep = 0; rep < 2; rep++) {
            int i = t + rep * 256;
            int k = i >> 4, nc = i & 15;
            float4 v = *(const float4*)(W1 + (size_t)(k0 + k) * (2 * SD) + n0 + nc * 4);
            *(float4*)&Bs[k][nc * 4] = v;
        }
        __syncthreads();
        #pragma unroll 8
        for (int k = 0; k < KT; k++) {
            float a0 = As[mi * 2 + 0][k], a1 = As[mi * 2 + 1][k];
            float4 bv4 = *(const float4*)&Bs[k][ni * 4];
            acc[0][0] += a0 * bv4.x; acc[0][1] += a0 * bv4.y;
            acc[0][2] += a0 * bv4.z; acc[0][3] += a0 * bv4.w;
            acc[1][0] += a1 * bv4.x; acc[1][1] += a1 * bv4.y;
            acc[1][2] += a1 * bv4.z; acc[1][3] += a1 * bv4.w;
        }
        __syncthreads();
    }
    #pragma unroll
    for (int ii = 0; ii < 2; ii++) {
        int m = m0 + mi * 2 + ii;
        #pragma unroll
        for (int u = 0; u < 4; u++) {
            int n = n0 + ni * 4 + u;
            gHid[(size_t)m * (2 * SD) + n] = fmaxf(acc[ii][u] + b1[n], 0.f);
        }
    }
}

// ---------------------------------------------------------------------------
// Kernel 7: out = gUpd + gHid @ W2 + b2. Grid (16, 4), tile 16x64, K=512.
// ---------------------------------------------------------------------------
__global__ void __launch_bounds__(256) mlp2_kernel(
    const float* __restrict__ W2, const float* __restrict__ b2,
    float* __restrict__ out)
{
    __shared__ float As[16][KT + 1];
    __shared__ float Bs[KT][68];
    int m0 = blockIdx.x * 16, n0 = blockIdx.y * 64;
    int t = threadIdx.x;
    int ni = t & 15, mi = t >> 4;   // 16 rows x (16 x 4 cols)
    float acc[4] = {0, 0, 0, 0};

    for (int k0 = 0; k0 < 2 * SD; k0 += KT) {
        if (t < 128) {
            int lm = t >> 3, lk = t & 7;
            float4 v = *(const float4*)(gHid + (size_t)(m0 + lm) * (2 * SD) + k0 + lk * 4);
            As[lm][lk * 4 + 0] = v.x; As[lm][lk * 4 + 1] = v.y;
            As[lm][lk * 4 + 2] = v.z; As[lm][lk * 4 + 3] = v.w;
        }
        #pragma unroll
        for (int rep = 0; rep < 2; rep++) {
            int i = t + rep * 256;
            int k = i >> 4, nc = i & 15;
            float4 v = *(const float4*)(W2 + (size_t)(k0 + k) * SD + n0 + nc * 4);
            *(float4*)&Bs[k][nc * 4] = v;
        }
        __syncthreads();
        #pragma unroll 8
        for (int k = 0; k < KT; k++) {
            float a = As[mi][k];
            float4 bv4 = *(const float4*)&Bs[k][ni * 4];
            acc[0] += a * bv4.x; acc[1] += a * bv4.y;
            acc[2] += a * bv4.z; acc[3] += a * bv4.w;
        }
        __syncthreads();
    }
    int m = m0 + mi;
    #pragma unroll
    for (int u = 0; u < 4; u++) {
        int n = n0 + ni * 4 + u;
        out[(size_t)m * SD + n] = gUpd[(size_t)m * SD + n] + acc[u] + b2[n];
    }
}

// ---------------------------------------------------------------------------
extern "C" void kernel_launch(void* const* d_in, const int* in_sizes, int n_in,
                              void* d_out, int out_size)
{
    const float* features = (const float*)d_in[0];
    const float* slots    = (const float*)d_in[1];
    const float* Wq   = (const float*)d_in[2];
    const float* bq   = (const float*)d_in[3];
    const float* Wk   = (const float*)d_in[4];
    const float* bk   = (const float*)d_in[5];
    const float* Wv   = (const float*)d_in[6];
    const float* bv   = (const float*)d_in[7];
    const float* W_ih = (const float*)d_in[8];
    const float* b_ih = (const float*)d_in[9];
    const float* W_hh = (const float*)d_in[10];
    const float* b_hh = (const float*)d_in[11];
    const float* g_pre  = (const float*)d_in[12];
    const float* b_pre  = (const float*)d_in[13];
    const float* g_post = (const float*)d_in[14];
    const float* b_post = (const float*)d_in[15];
    const float* W1 = (const float*)d_in[16];
    const float* b1 = (const float*)d_in[17];
    const float* W2 = (const float*)d_in[18];
    const float* b2 = (const float*)d_in[19];
    float* out = (float*)d_out;

    prep_kernel<<<BB * 2, 256>>>(slots, Wq, bq, Wk, bk, g_pre, b_pre);

    size_t smem = (size_t)(CC * FST + CC * NJ + NJ * AST) * sizeof(float);
    cudaFuncSetAttribute(main_kernel, cudaFuncAttributeMaxDynamicSharedMemorySize, (int)smem);
    main_kernel<<<dim3(NPIX / TILE_N, BB), 256, smem>>>(features);

    agg_kernel<<<BB * NH, 256>>>(Wv, bv);
    gru_gemm_kernel<<<dim3(NROWS / 32, SD / 32, 2), 256>>>(slots, W_ih, W_hh);
    gru_fin_kernel<<<NROWS / 8, 256>>>(slots, b_ih, b_hh, g_post, b_post);
    mlp1_kernel<<<dim3(NROWS / 32, (2 * SD) / 64), 256>>>(W1, b1);
    mlp2_kernel<<<dim3(NROWS / 16, SD / 64), 256>>>(W2, b2, out);
}